// round 13
// baseline (speedup 1.0000x reference)
#include <cuda_runtime.h>

// Problem constants (fixed shapes for this problem instance)
#define BB 4
#define NV 8192
#define NF 8192
#define NP 2048
#define MIN_DIST 0.1f

#define CHUNK 128           // faces per shared-memory tile
#define NCHUNK (NF / CHUNK) // 64
#define THREADS 128
#define NPTS 4              // points per thread
#define PTS_PER_BLOCK (THREADS * NPTS)        // 512
#define PBLOCKS (NP / PTS_PER_BLOCK)          // 4
#define TOTAL_BLOCKS (PBLOCKS * NCHUNK * BB)  // 1024

// Scratch (no allocations allowed in kernel_launch)
// Face planes, PAIR-INTERLEAVED: face pair q (faces 2q,2q+1):
//   [q*8+0,1]=x0,x1  [2,3]=y0,y1  [4,5]=z0,z1  [6,7]=off0,off1
__device__ float        g_facep[BB * NF * 4];
__device__ unsigned int g_minbits[BB * NP]; // unsigned-min of s-bits over faces
__device__ unsigned int g_ctr;              // last-block counter (reset each run)

// ---------------------------------------------------------------------------
// f32x2 helpers (Blackwell packed fp32; FFMA2 only reachable via PTX)
// ---------------------------------------------------------------------------
__device__ __forceinline__ unsigned long long fma2(unsigned long long a,
                                                   unsigned long long b,
                                                   unsigned long long c) {
    unsigned long long d;
    asm("fma.rn.f32x2 %0, %1, %2, %3;" : "=l"(d) : "l"(a), "l"(b), "l"(c));
    return d;
}
__device__ __forceinline__ unsigned long long bcast2(float v) {
    unsigned long long d;
    asm("mov.b64 %0, {%1, %1};" : "=l"(d) : "f"(v));
    return d;
}
__device__ __forceinline__ unsigned int umin2(unsigned int a, unsigned int b) {
    return a < b ? a : b; // IMNMX.U32
}

// ---------------------------------------------------------------------------
// Kernel 1: plane precompute, 4 THREADS PER FACE (c = x,y,z,offset-slot).
// Each thread gathers only its coordinate; dot products via 4-lane shfl.xor.
// Also inits g_minbits (first BB*NP threads).
// ---------------------------------------------------------------------------
__global__ __launch_bounds__(256)
void prep_kernel(const float* __restrict__ mesh_V,
                 const float* __restrict__ mesh_FN,
                 const int*   __restrict__ mesh_F) {
    int t = blockIdx.x * blockDim.x + threadIdx.x; // 0 .. BB*NF*4-1
    if (t < BB * NP) g_minbits[t] = 0xFFFFFFFFu;

    int f = t >> 2;        // face id (0 .. BB*NF-1)
    int c = t & 3;         // coordinate lane (3 = offset slot)
    if (f >= BB * NF) return;

    int b = f / NF;
    const int* Fp = mesh_F + 3 * f;
    int i0 = Fp[0], i1 = Fp[1], i2 = Fp[2];
    const float* Vb = mesh_V + (size_t)b * NV * 3;

    float cc = 0.0f, nc = 0.0f;
    if (c < 3) {
        cc = (Vb[3 * i0 + c] + Vb[3 * i1 + c] + Vb[3 * i2 + c]) * (1.0f / 3.0f);
        nc = mesh_FN[3 * f + c];
    }

    // 4-lane group sums (groups are lane-aligned: lanes 4k..4k+3)
    float p  = cc * nc;
    float nn = nc * nc;
    p  += __shfl_xor_sync(0xFFFFFFFFu, p, 1);
    p  += __shfl_xor_sync(0xFFFFFFFFu, p, 2);
    nn += __shfl_xor_sync(0xFFFFFFFFu, nn, 1);
    nn += __shfl_xor_sync(0xFFFFFFFFu, nn, 2);

    float s = sqrtf(nn);
    // s' = ||fn||*(dot(p,fn) - dot(c,fn) + MIN_DIST) => s'^2 == signed^2*fnsq
    float outv = (c == 3) ? (MIN_DIST - p) * s : nc * s;

    size_t base = ((size_t)(f >> 1)) * 8 + (f & 1);
    g_facep[base + 2 * c] = outv;
}

// ---------------------------------------------------------------------------
// Kernel 2: main loop + fused finalize. grid = (PBLOCKS, NCHUNK, BB), 128 thr.
// Each thread: 4 points; each f32x2 lane: 2 faces. 2 LDS.128 amortized over
// 256 point-face pairs per warp-iteration -> fma-pipe-bound, not LDS-bound.
// Unsigned-min over raw float bits: nonneg floats sort as unsigned; negatives
// sort above all nonnegs -> sign bit of result set iff ALL signed dists < 0.
// Last finishing block reduces g_minbits -> scalar mean.
// ---------------------------------------------------------------------------
__global__ __launch_bounds__(THREADS)
void dist_kernel(const float* __restrict__ points,
                 const int*   __restrict__ ext,
                 float*       __restrict__ out) {
    __shared__ float sf[CHUNK * 4]; // 2 KB pair-interleaved

    const int b   = blockIdx.z;
    const int tid = threadIdx.x;
    const int pb  = blockIdx.x * PTS_PER_BLOCK + tid;

    const float* pp = points + (size_t)b * NP * 3;
    unsigned long long PX[NPTS], PY[NPTS], PZ[NPTS];
#pragma unroll
    for (int k = 0; k < NPTS; k++) {
        int p = pb + k * THREADS;
        PX[k] = bcast2(pp[3 * p + 0]);
        PY[k] = bcast2(pp[3 * p + 1]);
        PZ[k] = bcast2(pp[3 * p + 2]);
    }

    {
        const float4* src = (const float4*)(g_facep + (size_t)(b * NF + blockIdx.y * CHUNK) * 4);
        float4* dst = (float4*)sf;
#pragma unroll
        for (int j = tid; j < CHUNK; j += THREADS)
            dst[j] = src[j];
    }
    __syncthreads();

    const ulonglong2* sp = (const ulonglong2*)sf; // 16B: (x0x1,y0y1) then (z0z1,w0w1)
    unsigned int ml[NPTS], mh[NPTS];
#pragma unroll
    for (int k = 0; k < NPTS; k++) { ml[k] = 0xFFFFFFFFu; mh[k] = 0xFFFFFFFFu; }

#pragma unroll 4
    for (int q = 0; q < CHUNK / 2; q++) {
        ulonglong2 xy = sp[q * 2 + 0];
        ulonglong2 zw = sp[q * 2 + 1];
#pragma unroll
        for (int k = 0; k < NPTS; k++) {
            unsigned long long s =
                fma2(PX[k], xy.x, fma2(PY[k], xy.y, fma2(PZ[k], zw.x, zw.y)));
            ml[k] = umin2(ml[k], (unsigned int)s);
            mh[k] = umin2(mh[k], (unsigned int)(s >> 32));
        }
    }

#pragma unroll
    for (int k = 0; k < NPTS; k++)
        atomicMin(&g_minbits[b * NP + pb + k * THREADS], umin2(ml[k], mh[k]));

    // ---- last-block-done finalize ----
    __shared__ bool is_last;
    __syncthreads(); // all atomics of this block issued
    if (tid == 0) {
        __threadfence();
        unsigned int done = atomicAdd(&g_ctr, 1u);
        is_last = (done == TOTAL_BLOCKS - 1);
    }
    __syncthreads();
    if (!is_last) return;

    __shared__ float red[THREADS];
    float sum = 0.0f;
#pragma unroll 4
    for (int i = tid; i < BB * NP; i += THREADS) {
        unsigned int bits = __ldcg(&g_minbits[i]); // atomics live in L2
        // sign bit set => every signed distance negative => inside
        bool inside = (ext[i] == 0) || (bits & 0x80000000u);
        float m = __uint_as_float(bits);
        sum += inside ? 0.0f : m * m;
    }
    red[tid] = sum;
    __syncthreads();
#pragma unroll
    for (int s = THREADS / 2; s > 0; s >>= 1) {
        if (tid < s) red[tid] += red[tid + s];
        __syncthreads();
    }
    if (tid == 0) {
        out[0] = red[0] * (1.0f / (float)(BB * NP));
        g_ctr = 0; // restore for next graph replay (deterministic)
    }
}

// ---------------------------------------------------------------------------
extern "C" void kernel_launch(void* const* d_in, const int* in_sizes, int n_in,
                              void* d_out, int out_size) {
    const float* mesh_V  = (const float*)d_in[0];
    const float* points  = (const float*)d_in[1];
    const float* mesh_FN = (const float*)d_in[2];
    const int*   mesh_F  = (const int*)d_in[3];
    const int*   exterior = (const int*)d_in[4];
    float* out = (float*)d_out;

    (void)in_sizes; (void)n_in; (void)out_size;

    prep_kernel<<<(BB * NF * 4 + 255) / 256, 256>>>(mesh_V, mesh_FN, mesh_F);

    dim3 grid(PBLOCKS, NCHUNK, BB);
    dist_kernel<<<grid, THREADS>>>(points, exterior, out);
}